// round 7
// baseline (speedup 1.0000x reference)
#include <cuda_runtime.h>
#include <cstdint>

// Problem constants
#define NTOK   8192        // B*S = 4*2048
#define DMODEL 1024
#define NEXP   8
#define HID    2048
#define TOPK   2
#define TM     128
#define TN     128
#define TKK    8
#define MAXR   (NTOK*TOPK + NEXP*TM)   // 17408
#define OUT_ELEMS (NTOK*DMODEL)

// ---------------- device scratch (no allocation allowed) ----------------
__device__ int   g_tope[NTOK*2];
__device__ float g_topp[NTOK*2];
__device__ int   g_pos[NTOK*2];
__device__ int   g_perm_tok[MAXR];
__device__ int   g_fcount[NEXP];
__device__ int   g_scount[NEXP];
__device__ int   g_off[NEXP+1];
__device__ int   g_cursor[NEXP];
__device__ float g_blockP[(NTOK/8)*NEXP];
__device__ float g_hidden[(size_t)MAXR*HID];
__device__ float g_expout[(size_t)MAXR*DMODEL];

// ---------------- init ----------------
__global__ void init_kernel() {
    int i = blockIdx.x * blockDim.x + threadIdx.x;
    if (i < MAXR) g_perm_tok[i] = -1;
    if (i < NEXP) { g_fcount[i] = 0; g_scount[i] = 0; }
}

// ---------------- router ----------------
__global__ void __launch_bounds__(256) router_kernel(const float* __restrict__ x,
                                                     const float* __restrict__ gate_w) {
    __shared__ float sg[NEXP * DMODEL];
    __shared__ float warpP[8][NEXP];
    int tid = threadIdx.x;
    for (int i = tid; i < NEXP * DMODEL; i += 256) sg[i] = gate_w[i];
    __syncthreads();

    int warp = tid >> 5, lane = tid & 31;
    int t = blockIdx.x * 8 + warp;
    const float* xr = x + (size_t)t * DMODEL;

    float acc[NEXP];
#pragma unroll
    for (int e = 0; e < NEXP; e++) acc[e] = 0.f;
    for (int j = 0; j < DMODEL / 32; j++) {
        float v = xr[j * 32 + lane];
#pragma unroll
        for (int e = 0; e < NEXP; e++) acc[e] += v * sg[e * DMODEL + j * 32 + lane];
    }
#pragma unroll
    for (int e = 0; e < NEXP; e++)
#pragma unroll
        for (int o = 16; o > 0; o >>= 1) acc[e] += __shfl_xor_sync(0xffffffffu, acc[e], o);

    if (lane == 0) {
        float m = acc[0];
#pragma unroll
        for (int e = 1; e < NEXP; e++) m = fmaxf(m, acc[e]);
        float p[NEXP], s = 0.f;
#pragma unroll
        for (int e = 0; e < NEXP; e++) { p[e] = __expf(acc[e] - m); s += p[e]; }
        float inv = 1.f / s;
#pragma unroll
        for (int e = 0; e < NEXP; e++) p[e] *= inv;
        int i1 = 0;
#pragma unroll
        for (int e = 1; e < NEXP; e++) if (p[e] > p[i1]) i1 = e;
        int i2 = (i1 == 0) ? 1 : 0;
#pragma unroll
        for (int e = 0; e < NEXP; e++) if (e != i1 && p[e] > p[i2]) i2 = e;
        float s2 = p[i1] + p[i2];
        g_tope[t * 2 + 0] = i1;  g_topp[t * 2 + 0] = p[i1] / s2;
        g_tope[t * 2 + 1] = i2;  g_topp[t * 2 + 1] = p[i2] / s2;
        atomicAdd(&g_fcount[i1], 1);
        atomicAdd(&g_scount[i1], 1);
        atomicAdd(&g_scount[i2], 1);
#pragma unroll
        for (int e = 0; e < NEXP; e++) warpP[warp][e] = p[e];
    }
    __syncthreads();
    if (tid < NEXP) {
        float s = 0.f;
#pragma unroll
        for (int w = 0; w < 8; w++) s += warpP[w][tid];
        g_blockP[blockIdx.x * NEXP + tid] = s;
    }
}

// ---------------- offsets ----------------
__global__ void offsets_kernel() {
    if (threadIdx.x == 0) {
        int o = 0;
        for (int e = 0; e < NEXP; e++) {
            g_off[e] = o;
            g_cursor[e] = o;
            o += ((g_scount[e] + TM - 1) / TM) * TM;
        }
        g_off[NEXP] = o;
    }
}

// ---------------- scatter ----------------
__global__ void scatter_kernel() {
    int t = blockIdx.x * blockDim.x + threadIdx.x;
    if (t >= NTOK) return;
#pragma unroll
    for (int k = 0; k < 2; k++) {
        int e = g_tope[t * 2 + k];
        int pos = atomicAdd(&g_cursor[e], 1);
        g_perm_tok[pos] = t;
        g_pos[t * 2 + k] = pos;
    }
}

// ---------------- FFMA2 helper ----------------
__device__ __forceinline__ void ffma2(unsigned long long& c, unsigned long long a,
                                      unsigned long long b) {
    asm("fma.rn.f32x2 %0, %1, %2, %0;" : "+l"(c) : "l"(a), "l"(b));
}

// ---------------- GEMM1: hidden = relu(gather(x) @ w1[e]) ----------------
__global__ void __launch_bounds__(256, 2) gemm1_kernel(const float* __restrict__ x,
                                                       const float* __restrict__ w1) {
    __shared__ float As[2][TKK][2 * TM];   // duplicated pairs for f32x2
    __shared__ float Bs[2][TKK][TN];
    __shared__ int   s_tok[TM];

    int row0 = blockIdx.y * TM;
    if (row0 >= g_off[NEXP]) return;
    int e = 0;
#pragma unroll
    for (int q = 1; q < NEXP; q++) if (row0 >= g_off[q]) e = q;
    const float* B = w1 + (size_t)e * DMODEL * HID;
    int bn0 = blockIdx.x * TN;
    int tid = threadIdx.x;
    if (tid < TM) s_tok[tid] = g_perm_tok[row0 + tid];
    __syncthreads();

    int ar = tid >> 1, ak = (tid & 1) * 4;
    int bk = tid >> 5, bn = (tid & 31) * 4;
    int tx = tid & 15, ty = tid >> 4;
    int tokA = s_tok[ar];
    const float* Arow = (tokA >= 0) ? (x + (size_t)tokA * DMODEL + ak) : x;

    unsigned long long acc[8][4];
#pragma unroll
    for (int i = 0; i < 8; i++)
#pragma unroll
        for (int j = 0; j < 4; j++) acc[i][j] = 0ull;

    // prologue: tile 0
    {
        float4 av = make_float4(0.f, 0.f, 0.f, 0.f);
        if (tokA >= 0) av = *(const float4*)(Arow + 0);
        *(float2*)&As[0][ak + 0][2 * ar] = make_float2(av.x, av.x);
        *(float2*)&As[0][ak + 1][2 * ar] = make_float2(av.y, av.y);
        *(float2*)&As[0][ak + 2][2 * ar] = make_float2(av.z, av.z);
        *(float2*)&As[0][ak + 3][2 * ar] = make_float2(av.w, av.w);
        float4 bv = *(const float4*)(B + (size_t)bk * HID + bn0 + bn);
        *(float4*)&Bs[0][bk][bn] = bv;
    }
    __syncthreads();

    const int nk = DMODEL / TKK;   // 128
    for (int kt = 0; kt < nk; kt++) {
        int buf = kt & 1;
        float4 av2, bv2;
        bool more = (kt + 1 < nk);
        if (more) {
            av2 = make_float4(0.f, 0.f, 0.f, 0.f);
            if (tokA >= 0) av2 = *(const float4*)(Arow + (kt + 1) * TKK);
            bv2 = *(const float4*)(B + (size_t)((kt + 1) * TKK + bk) * HID + bn0 + bn);
        }
#pragma unroll
        for (int kk = 0; kk < TKK; kk++) {
            unsigned long long a8[8], b4[4];
#pragma unroll
            for (int i = 0; i < 4; i++) {
                ulonglong2 t = *(const ulonglong2*)&As[buf][kk][2 * (ty * 8 + 2 * i)];
                a8[2 * i] = t.x;  a8[2 * i + 1] = t.y;
            }
            {
                ulonglong2 t0 = *(const ulonglong2*)&Bs[buf][kk][tx * 8];
                ulonglong2 t1 = *(const ulonglong2*)&Bs[buf][kk][tx * 8 + 4];
                b4[0] = t0.x;  b4[1] = t0.y;  b4[2] = t1.x;  b4[3] = t1.y;
            }
#pragma unroll
            for (int i = 0; i < 8; i++)
#pragma unroll
                for (int j = 0; j < 4; j++) ffma2(acc[i][j], a8[i], b4[j]);
        }
        if (more) {
            int nb = buf ^ 1;
            *(float2*)&As[nb][ak + 0][2 * ar] = make_float2(av2.x, av2.x);
            *(float2*)&As[nb][ak + 1][2 * ar] = make_float2(av2.y, av2.y);
            *(float2*)&As[nb][ak + 2][2 * ar] = make_float2(av2.z, av2.z);
            *(float2*)&As[nb][ak + 3][2 * ar] = make_float2(av2.w, av2.w);
            *(float4*)&Bs[nb][bk][bn] = bv2;
            __syncthreads();
        }
    }

    // epilogue: relu + store
#pragma unroll
    for (int i = 0; i < 8; i++) {
        int row = row0 + ty * 8 + i;
        float* dst = g_hidden + (size_t)row * HID + bn0 + tx * 8;
#pragma unroll
        for (int j = 0; j < 4; j++) {
            float2 v = *(float2*)&acc[i][j];
            v.x = fmaxf(v.x, 0.f);
            v.y = fmaxf(v.y, 0.f);
            *(float2*)(dst + 2 * j) = v;
        }
    }
}

// ---------------- GEMM2: expout = hidden @ w2[e] ----------------
__global__ void __launch_bounds__(256, 2) gemm2_kernel(const float* __restrict__ w2) {
    __shared__ float As[2][TKK][2 * TM];
    __shared__ float Bs[2][TKK][TN];

    int row0 = blockIdx.y * TM;
    if (row0 >= g_off[NEXP]) return;
    int e = 0;
#pragma unroll
    for (int q = 1; q < NEXP; q++) if (row0 >= g_off[q]) e = q;
    const float* B = w2 + (size_t)e * HID * DMODEL;
    int bn0 = blockIdx.x * TN;
    int tid = threadIdx.x;

    int ar = tid >> 1, ak = (tid & 1) * 4;
    int bk = tid >> 5, bn = (tid & 31) * 4;
    int tx = tid & 15, ty = tid >> 4;
    const float* Arow = g_hidden + (size_t)(row0 + ar) * HID + ak;

    unsigned long long acc[8][4];
#pragma unroll
    for (int i = 0; i < 8; i++)
#pragma unroll
        for (int j = 0; j < 4; j++) acc[i][j] = 0ull;

    {
        float4 av = *(const float4*)(Arow + 0);
        *(float2*)&As[0][ak + 0][2 * ar] = make_float2(av.x, av.x);
        *(float2*)&As[0][ak + 1][2 * ar] = make_float2(av.y, av.y);
        *(float2*)&As[0][ak + 2][2 * ar] = make_float2(av.z, av.z);
        *(float2*)&As[0][ak + 3][2 * ar] = make_float2(av.w, av.w);
        float4 bv = *(const float4*)(B + (size_t)bk * DMODEL + bn0 + bn);
        *(float4*)&Bs[0][bk][bn] = bv;
    }
    __syncthreads();

    const int nk = HID / TKK;   // 256
    for (int kt = 0; kt < nk; kt++) {
        int buf = kt & 1;
        float4 av2, bv2;
        bool more = (kt + 1 < nk);
        if (more) {
            av2 = *(const float4*)(Arow + (kt + 1) * TKK);
            bv2 = *(const float4*)(B + (size_t)((kt + 1) * TKK + bk) * DMODEL + bn0 + bn);
        }
#pragma unroll
        for (int kk = 0; kk < TKK; kk++) {
            unsigned long long a8[8], b4[4];
#pragma unroll
            for (int i = 0; i < 4; i++) {
                ulonglong2 t = *(const ulonglong2*)&As[buf][kk][2 * (ty * 8 + 2 * i)];
                a8[2 * i] = t.x;  a8[2 * i + 1] = t.y;
            }
            {
                ulonglong2 t0 = *(const ulonglong2*)&Bs[buf][kk][tx * 8];
                ulonglong2 t1 = *(const ulonglong2*)&Bs[buf][kk][tx * 8 + 4];
                b4[0] = t0.x;  b4[1] = t0.y;  b4[2] = t1.x;  b4[3] = t1.y;
            }
#pragma unroll
            for (int i = 0; i < 8; i++)
#pragma unroll
                for (int j = 0; j < 4; j++) ffma2(acc[i][j], a8[i], b4[j]);
        }
        if (more) {
            int nb = buf ^ 1;
            *(float2*)&As[nb][ak + 0][2 * ar] = make_float2(av2.x, av2.x);
            *(float2*)&As[nb][ak + 1][2 * ar] = make_float2(av2.y, av2.y);
            *(float2*)&As[nb][ak + 2][2 * ar] = make_float2(av2.z, av2.z);
            *(float2*)&As[nb][ak + 3][2 * ar] = make_float2(av2.w, av2.w);
            *(float4*)&Bs[nb][bk][bn] = bv2;
            __syncthreads();
        }
    }

#pragma unroll
    for (int i = 0; i < 8; i++) {
        int row = row0 + ty * 8 + i;
        float* dst = g_expout + (size_t)row * DMODEL + bn0 + tx * 8;
#pragma unroll
        for (int j = 0; j < 4; j++) {
            float2 v = *(float2*)&acc[i][j];
            *(float2*)(dst + 2 * j) = v;
        }
    }
}

// ---------------- combine ----------------
__global__ void combine_kernel(float* __restrict__ out) {
    int idx = blockIdx.x * blockDim.x + threadIdx.x;
    if (idx >= NTOK * (DMODEL / 4)) return;
    int t = idx >> 8;
    int c = idx & 255;
    float p0 = g_topp[t * 2 + 0], p1 = g_topp[t * 2 + 1];
    size_t r0 = (size_t)g_pos[t * 2 + 0] * (DMODEL / 4);
    size_t r1 = (size_t)g_pos[t * 2 + 1] * (DMODEL / 4);
    const float4* buf = (const float4*)g_expout;
    float4 a = buf[r0 + c];
    float4 b = buf[r1 + c];
    float4 o;
    o.x = p0 * a.x + p1 * b.x;
    o.y = p0 * a.y + p1 * b.y;
    o.z = p0 * a.z + p1 * b.z;
    o.w = p0 * a.w + p1 * b.w;
    ((float4*)out)[idx] = o;
}

// ---------------- aux loss ----------------
__global__ void aux_kernel(float* __restrict__ out, int out_size) {
    __shared__ float P[NEXP];
    int e = threadIdx.x;
    if (e < NEXP) {
        float s = 0.f;
        for (int b = 0; b < NTOK / 8; b++) s += g_blockP[b * NEXP + e];
        P[e] = s * (1.0f / NTOK);
    }
    __syncthreads();
    if (threadIdx.x == 0 && out_size > OUT_ELEMS) {
        float aux = 0.f;
        for (int q = 0; q < NEXP; q++)
            aux += ((float)g_fcount[q] * (1.0f / NTOK)) * P[q];
        aux *= 0.01f * NEXP;
        out[OUT_ELEMS] = aux;
    }
}

// ---------------- launch ----------------
extern "C" void kernel_launch(void* const* d_in, const int* in_sizes, int n_in,
                              void* d_out, int out_size) {
    const float* x      = (const float*)d_in[0];
    const float* gate_w = (const float*)d_in[1];
    const float* w1     = (const float*)d_in[2];
    const float* w2     = (const float*)d_in[3];
    float* out = (float*)d_out;

    init_kernel<<<(MAXR + 255) / 256, 256>>>();
    router_kernel<<<NTOK / 8, 256>>>(x, gate_w);
    offsets_kernel<<<1, 32>>>();
    scatter_kernel<<<(NTOK + 255) / 256, 256>>>();

    dim3 g1(HID / TN, MAXR / TM);      // (16, 136)
    gemm1_kernel<<<g1, 256>>>(x, w1);
    dim3 g2(DMODEL / TN, MAXR / TM);   // (8, 136)
    gemm2_kernel<<<g2, 256>>>(w2);

    combine_kernel<<<(NTOK * (DMODEL / 4) + 255) / 256, 256>>>(out);
    aux_kernel<<<1, 32>>>(out, out_size);
}

// round 8
// speedup vs baseline: 1.0491x; 1.0491x over previous
#include <cuda_runtime.h>
#include <cstdint>

// Problem constants
#define NTOK   8192        // B*S = 4*2048
#define DMODEL 1024
#define NEXP   8
#define HID    2048
#define TOPK   2
#define TM     128
#define TN     128
#define TKK    16
#define MAXR   (NTOK*TOPK + NEXP*TM)   // 17408
#define OUT_ELEMS (NTOK*DMODEL)

// ---------------- device scratch (no allocation allowed) ----------------
__device__ int   g_tope[NTOK*2];
__device__ float g_topp[NTOK*2];
__device__ int   g_pos[NTOK*2];
__device__ int   g_perm_tok[MAXR];
__device__ int   g_fcount[NEXP];
__device__ int   g_scount[NEXP];
__device__ int   g_off[NEXP+1];
__device__ int   g_cursor[NEXP];
__device__ float g_blockP[(NTOK/8)*NEXP];
__device__ float g_hidden[(size_t)MAXR*HID];
__device__ float g_expout[(size_t)MAXR*DMODEL];

// ---------------- init ----------------
__global__ void init_kernel() {
    int i = blockIdx.x * blockDim.x + threadIdx.x;
    if (i < MAXR) g_perm_tok[i] = -1;
    if (i < NEXP) { g_fcount[i] = 0; g_scount[i] = 0; }
}

// ---------------- router ----------------
__global__ void __launch_bounds__(256) router_kernel(const float* __restrict__ x,
                                                     const float* __restrict__ gate_w) {
    __shared__ float sg[NEXP * DMODEL];
    __shared__ float warpP[8][NEXP];
    int tid = threadIdx.x;
    for (int i = tid; i < NEXP * DMODEL; i += 256) sg[i] = gate_w[i];
    __syncthreads();

    int warp = tid >> 5, lane = tid & 31;
    int t = blockIdx.x * 8 + warp;
    const float* xr = x + (size_t)t * DMODEL;

    float acc[NEXP];
#pragma unroll
    for (int e = 0; e < NEXP; e++) acc[e] = 0.f;
    for (int j = 0; j < DMODEL / 32; j++) {
        float v = xr[j * 32 + lane];
#pragma unroll
        for (int e = 0; e < NEXP; e++) acc[e] += v * sg[e * DMODEL + j * 32 + lane];
    }
#pragma unroll
    for (int e = 0; e < NEXP; e++)
#pragma unroll
        for (int o = 16; o > 0; o >>= 1) acc[e] += __shfl_xor_sync(0xffffffffu, acc[e], o);

    if (lane == 0) {
        float m = acc[0];
#pragma unroll
        for (int e = 1; e < NEXP; e++) m = fmaxf(m, acc[e]);
        float p[NEXP], s = 0.f;
#pragma unroll
        for (int e = 0; e < NEXP; e++) { p[e] = __expf(acc[e] - m); s += p[e]; }
        float inv = 1.f / s;
#pragma unroll
        for (int e = 0; e < NEXP; e++) p[e] *= inv;
        int i1 = 0;
#pragma unroll
        for (int e = 1; e < NEXP; e++) if (p[e] > p[i1]) i1 = e;
        int i2 = (i1 == 0) ? 1 : 0;
#pragma unroll
        for (int e = 0; e < NEXP; e++) if (e != i1 && p[e] > p[i2]) i2 = e;
        float s2 = p[i1] + p[i2];
        g_tope[t * 2 + 0] = i1;  g_topp[t * 2 + 0] = p[i1] / s2;
        g_tope[t * 2 + 1] = i2;  g_topp[t * 2 + 1] = p[i2] / s2;
        atomicAdd(&g_fcount[i1], 1);
        atomicAdd(&g_scount[i1], 1);
        atomicAdd(&g_scount[i2], 1);
#pragma unroll
        for (int e = 0; e < NEXP; e++) warpP[warp][e] = p[e];
    }
    __syncthreads();
    if (tid < NEXP) {
        float s = 0.f;
#pragma unroll
        for (int w = 0; w < 8; w++) s += warpP[w][tid];
        g_blockP[blockIdx.x * NEXP + tid] = s;
    }
}

// ---------------- offsets ----------------
__global__ void offsets_kernel() {
    if (threadIdx.x == 0) {
        int o = 0;
        for (int e = 0; e < NEXP; e++) {
            g_off[e] = o;
            g_cursor[e] = o;
            o += ((g_scount[e] + TM - 1) / TM) * TM;
        }
        g_off[NEXP] = o;
    }
}

// ---------------- scatter ----------------
__global__ void scatter_kernel() {
    int t = blockIdx.x * blockDim.x + threadIdx.x;
    if (t >= NTOK) return;
#pragma unroll
    for (int k = 0; k < 2; k++) {
        int e = g_tope[t * 2 + k];
        int pos = atomicAdd(&g_cursor[e], 1);
        g_perm_tok[pos] = t;
        g_pos[t * 2 + k] = pos;
    }
}

// ---------------- FFMA2 helper ----------------
__device__ __forceinline__ void ffma2(unsigned long long& c, unsigned long long a,
                                      unsigned long long b) {
    asm("fma.rn.f32x2 %0, %1, %2, %0;" : "+l"(c) : "l"(a), "l"(b));
}

// ---------------- GEMM1: hidden = relu(gather(x) @ w1[e]) ----------------
__global__ void __launch_bounds__(256, 2) gemm1_kernel(const float* __restrict__ x,
                                                       const float* __restrict__ w1) {
    __shared__ float As[2][TKK][2 * TM];   // 32 KB: duplicated pairs for f32x2
    __shared__ float Bs[2][TKK][TN];       // 16 KB

    int row0 = blockIdx.y * TM;
    if (row0 >= g_off[NEXP]) return;
    int e = 0;
#pragma unroll
    for (int q = 1; q < NEXP; q++) if (row0 >= g_off[q]) e = q;
    const float* B = w1 + (size_t)e * DMODEL * HID;
    int bn0 = blockIdx.x * TN;
    int tid = threadIdx.x;

    int ar = tid >> 1, ak = (tid & 1) * 8;          // A: row ar, k-offset ak (0/8)
    int bk = tid >> 4, bn = (tid & 15) * 8;         // B: k-row bk (0..15), col bn
    int tx = tid & 15, ty = tid >> 4;
    int tokA = g_perm_tok[row0 + ar];
    const float* Arow = (tokA >= 0) ? (x + (size_t)tokA * DMODEL + ak) : x;

    unsigned long long acc[8][4];
#pragma unroll
    for (int i = 0; i < 8; i++)
#pragma unroll
        for (int j = 0; j < 4; j++) acc[i][j] = 0ull;

    // prologue: tile 0
    {
        float4 a0 = make_float4(0.f, 0.f, 0.f, 0.f), a1 = a0;
        if (tokA >= 0) { a0 = *(const float4*)(Arow); a1 = *(const float4*)(Arow + 4); }
#pragma unroll
        for (int j = 0; j < 4; j++) {
            float v0 = (&a0.x)[j], v1 = (&a1.x)[j];
            *(float2*)&As[0][ak + j][2 * ar] = make_float2(v0, v0);
            *(float2*)&As[0][ak + 4 + j][2 * ar] = make_float2(v1, v1);
        }
        const float* bp = B + (size_t)bk * HID + bn0 + bn;
        *(float4*)&Bs[0][bk][bn] = *(const float4*)bp;
        *(float4*)&Bs[0][bk][bn + 4] = *(const float4*)(bp + 4);
    }
    __syncthreads();

    const int nk = DMODEL / TKK;   // 64
    for (int kt = 0; kt < nk; kt++) {
        int buf = kt & 1;
        float4 a0n, a1n, b0n, b1n;
        bool more = (kt + 1 < nk);
        if (more) {
            a0n = make_float4(0.f, 0.f, 0.f, 0.f); a1n = a0n;
            if (tokA >= 0) {
                a0n = *(const float4*)(Arow + (kt + 1) * TKK);
                a1n = *(const float4*)(Arow + (kt + 1) * TKK + 4);
            }
            const float* bp = B + (size_t)((kt + 1) * TKK + bk) * HID + bn0 + bn;
            b0n = *(const float4*)bp;
            b1n = *(const float4*)(bp + 4);
        }
#pragma unroll
        for (int kk = 0; kk < TKK; kk++) {
            unsigned long long a8[8], b4[4];
#pragma unroll
            for (int i = 0; i < 4; i++) {
                ulonglong2 t = *(const ulonglong2*)&As[buf][kk][2 * (ty * 8 + 2 * i)];
                a8[2 * i] = t.x;  a8[2 * i + 1] = t.y;
            }
            {
                ulonglong2 t0 = *(const ulonglong2*)&Bs[buf][kk][tx * 8];
                ulonglong2 t1 = *(const ulonglong2*)&Bs[buf][kk][tx * 8 + 4];
                b4[0] = t0.x;  b4[1] = t0.y;  b4[2] = t1.x;  b4[3] = t1.y;
            }
#pragma unroll
            for (int i = 0; i < 8; i++)
#pragma unroll
                for (int j = 0; j < 4; j++) ffma2(acc[i][j], a8[i], b4[j]);
        }
        if (more) {
            int nb = buf ^ 1;
#pragma unroll
            for (int j = 0; j < 4; j++) {
                float v0 = (&a0n.x)[j], v1 = (&a1n.x)[j];
                *(float2*)&As[nb][ak + j][2 * ar] = make_float2(v0, v0);
                *(float2*)&As[nb][ak + 4 + j][2 * ar] = make_float2(v1, v1);
            }
            *(float4*)&Bs[nb][bk][bn] = b0n;
            *(float4*)&Bs[nb][bk][bn + 4] = b1n;
            __syncthreads();
        }
    }

    // epilogue: relu + store
#pragma unroll
    for (int i = 0; i < 8; i++) {
        int row = row0 + ty * 8 + i;
        float* dst = g_hidden + (size_t)row * HID + bn0 + tx * 8;
#pragma unroll
        for (int j = 0; j < 4; j++) {
            float2 v = *(float2*)&acc[i][j];
            v.x = fmaxf(v.x, 0.f);
            v.y = fmaxf(v.y, 0.f);
            *(float2*)(dst + 2 * j) = v;
        }
    }
}

// ---------------- GEMM2: expout = hidden @ w2[e] ----------------
__global__ void __launch_bounds__(256, 2) gemm2_kernel(const float* __restrict__ w2) {
    __shared__ float As[2][TKK][2 * TM];
    __shared__ float Bs[2][TKK][TN];

    int row0 = blockIdx.y * TM;
    if (row0 >= g_off[NEXP]) return;
    int e = 0;
#pragma unroll
    for (int q = 1; q < NEXP; q++) if (row0 >= g_off[q]) e = q;
    const float* B = w2 + (size_t)e * HID * DMODEL;
    int bn0 = blockIdx.x * TN;
    int tid = threadIdx.x;

    int ar = tid >> 1, ak = (tid & 1) * 8;
    int bk = tid >> 4, bn = (tid & 15) * 8;
    int tx = tid & 15, ty = tid >> 4;
    const float* Arow = g_hidden + (size_t)(row0 + ar) * HID + ak;

    unsigned long long acc[8][4];
#pragma unroll
    for (int i = 0; i < 8; i++)
#pragma unroll
        for (int j = 0; j < 4; j++) acc[i][j] = 0ull;

    {
        float4 a0 = *(const float4*)(Arow);
        float4 a1 = *(const float4*)(Arow + 4);
#pragma unroll
        for (int j = 0; j < 4; j++) {
            float v0 = (&a0.x)[j], v1 = (&a1.x)[j];
            *(float2*)&As[0][ak + j][2 * ar] = make_float2(v0, v0);
            *(float2*)&As[0][ak + 4 + j][2 * ar] = make_float2(v1, v1);
        }
        const float* bp = B + (size_t)bk * DMODEL + bn0 + bn;
        *(float4*)&Bs[0][bk][bn] = *(const float4*)bp;
        *(float4*)&Bs[0][bk][bn + 4] = *(const float4*)(bp + 4);
    }
    __syncthreads();

    const int nk = HID / TKK;   // 128
    for (int kt = 0; kt < nk; kt++) {
        int buf = kt & 1;
        float4 a0n, a1n, b0n, b1n;
        bool more = (kt + 1 < nk);
        if (more) {
            a0n = *(const float4*)(Arow + (kt + 1) * TKK);
            a1n = *(const float4*)(Arow + (kt + 1) * TKK + 4);
            const float* bp = B + (size_t)((kt + 1) * TKK + bk) * DMODEL + bn0 + bn;
            b0n = *(const float4*)bp;
            b1n = *(const float4*)(bp + 4);
        }
#pragma unroll
        for (int kk = 0; kk < TKK; kk++) {
            unsigned long long a8[8], b4[4];
#pragma unroll
            for (int i = 0; i < 4; i++) {
                ulonglong2 t = *(const ulonglong2*)&As[buf][kk][2 * (ty * 8 + 2 * i)];
                a8[2 * i] = t.x;  a8[2 * i + 1] = t.y;
            }
            {
                ulonglong2 t0 = *(const ulonglong2*)&Bs[buf][kk][tx * 8];
                ulonglong2 t1 = *(const ulonglong2*)&Bs[buf][kk][tx * 8 + 4];
                b4[0] = t0.x;  b4[1] = t0.y;  b4[2] = t1.x;  b4[3] = t1.y;
            }
#pragma unroll
            for (int i = 0; i < 8; i++)
#pragma unroll
                for (int j = 0; j < 4; j++) ffma2(acc[i][j], a8[i], b4[j]);
        }
        if (more) {
            int nb = buf ^ 1;
#pragma unroll
            for (int j = 0; j < 4; j++) {
                float v0 = (&a0n.x)[j], v1 = (&a1n.x)[j];
                *(float2*)&As[nb][ak + j][2 * ar] = make_float2(v0, v0);
                *(float2*)&As[nb][ak + 4 + j][2 * ar] = make_float2(v1, v1);
            }
            *(float4*)&Bs[nb][bk][bn] = b0n;
            *(float4*)&Bs[nb][bk][bn + 4] = b1n;
            __syncthreads();
        }
    }

#pragma unroll
    for (int i = 0; i < 8; i++) {
        int row = row0 + ty * 8 + i;
        float* dst = g_expout + (size_t)row * DMODEL + bn0 + tx * 8;
#pragma unroll
        for (int j = 0; j < 4; j++) {
            float2 v = *(float2*)&acc[i][j];
            *(float2*)(dst + 2 * j) = v;
        }
    }
}

// ---------------- combine ----------------
__global__ void combine_kernel(float* __restrict__ out) {
    int idx = blockIdx.x * blockDim.x + threadIdx.x;
    if (idx >= NTOK * (DMODEL / 4)) return;
    int t = idx >> 8;
    int c = idx & 255;
    float p0 = g_topp[t * 2 + 0], p1 = g_topp[t * 2 + 1];
    size_t r0 = (size_t)g_pos[t * 2 + 0] * (DMODEL / 4);
    size_t r1 = (size_t)g_pos[t * 2 + 1] * (DMODEL / 4);
    const float4* buf = (const float4*)g_expout;
    float4 a = buf[r0 + c];
    float4 b = buf[r1 + c];
    float4 o;
    o.x = p0 * a.x + p1 * b.x;
    o.y = p0 * a.y + p1 * b.y;
    o.z = p0 * a.z + p1 * b.z;
    o.w = p0 * a.w + p1 * b.w;
    ((float4*)out)[idx] = o;
}

// ---------------- aux loss ----------------
__global__ void aux_kernel(float* __restrict__ out, int out_size) {
    __shared__ float P[NEXP];
    int e = threadIdx.x;
    if (e < NEXP) {
        float s = 0.f;
        for (int b = 0; b < NTOK / 8; b++) s += g_blockP[b * NEXP + e];
        P[e] = s * (1.0f / NTOK);
    }
    __syncthreads();
    if (threadIdx.x == 0 && out_size > OUT_ELEMS) {
        float aux = 0.f;
        for (int q = 0; q < NEXP; q++)
            aux += ((float)g_fcount[q] * (1.0f / NTOK)) * P[q];
        aux *= 0.01f * NEXP;
        out[OUT_ELEMS] = aux;
    }
}

// ---------------- launch ----------------
extern "C" void kernel_launch(void* const* d_in, const int* in_sizes, int n_in,
                              void* d_out, int out_size) {
    const float* x      = (const float*)d_in[0];
    const float* gate_w = (const float*)d_in[1];
    const float* w1     = (const float*)d_in[2];
    const float* w2     = (const float*)d_in[3];
    float* out = (float*)d_out;

    init_kernel<<<(MAXR + 255) / 256, 256>>>();
    router_kernel<<<NTOK / 8, 256>>>(x, gate_w);
    offsets_kernel<<<1, 32>>>();
    scatter_kernel<<<(NTOK + 255) / 256, 256>>>();

    dim3 g1(HID / TN, MAXR / TM);      // (16, 136)
    gemm1_kernel<<<g1, 256>>>(x, w1);
    dim3 g2(DMODEL / TN, MAXR / TM);   // (8, 136)
    gemm2_kernel<<<g2, 256>>>(w2);

    combine_kernel<<<(NTOK * (DMODEL / 4) + 255) / 256, 256>>>(out);
    aux_kernel<<<1, 32>>>(out, out_size);
}

// round 9
// speedup vs baseline: 1.3200x; 1.2583x over previous
#include <cuda_runtime.h>
#include <cstdint>

// Problem constants
#define NTOK   8192        // B*S = 4*2048
#define DMODEL 1024
#define NEXP   8
#define HID    2048
#define TOPK   2
#define TM     128
#define TN     128
#define TKK    16
#define MAXR   (NTOK*TOPK + NEXP*TM)   // 17408
#define OUT_ELEMS (NTOK*DMODEL)

// ---------------- device scratch (no allocation allowed) ----------------
__device__ int   g_tope[NTOK*2];
__device__ float g_topp[NTOK*2];
__device__ int   g_pos[NTOK*2];
__device__ int   g_perm_tok[MAXR];
__device__ int   g_fcount[NEXP];
__device__ int   g_scount[NEXP];
__device__ int   g_off[NEXP+1];
__device__ int   g_cursor[NEXP];
__device__ float g_blockP[(NTOK/8)*NEXP];
__device__ float g_hidden[(size_t)MAXR*HID];
__device__ float g_expout[(size_t)MAXR*DMODEL];

// ---------------- init ----------------
__global__ void init_kernel() {
    int i = blockIdx.x * blockDim.x + threadIdx.x;
    if (i < MAXR) g_perm_tok[i] = -1;
    if (i < NEXP) { g_fcount[i] = 0; g_scount[i] = 0; }
}

// ---------------- router ----------------
__global__ void __launch_bounds__(256) router_kernel(const float* __restrict__ x,
                                                     const float* __restrict__ gate_w) {
    __shared__ float sg[NEXP * DMODEL];
    __shared__ float warpP[8][NEXP];
    int tid = threadIdx.x;
    for (int i = tid; i < NEXP * DMODEL; i += 256) sg[i] = gate_w[i];
    __syncthreads();

    int warp = tid >> 5, lane = tid & 31;
    int t = blockIdx.x * 8 + warp;
    const float* xr = x + (size_t)t * DMODEL;

    float acc[NEXP];
#pragma unroll
    for (int e = 0; e < NEXP; e++) acc[e] = 0.f;
    for (int j = 0; j < DMODEL / 32; j++) {
        float v = xr[j * 32 + lane];
#pragma unroll
        for (int e = 0; e < NEXP; e++) acc[e] += v * sg[e * DMODEL + j * 32 + lane];
    }
#pragma unroll
    for (int e = 0; e < NEXP; e++)
#pragma unroll
        for (int o = 16; o > 0; o >>= 1) acc[e] += __shfl_xor_sync(0xffffffffu, acc[e], o);

    if (lane == 0) {
        float m = acc[0];
#pragma unroll
        for (int e = 1; e < NEXP; e++) m = fmaxf(m, acc[e]);
        float p[NEXP], s = 0.f;
#pragma unroll
        for (int e = 0; e < NEXP; e++) { p[e] = __expf(acc[e] - m); s += p[e]; }
        float inv = 1.f / s;
#pragma unroll
        for (int e = 0; e < NEXP; e++) p[e] *= inv;
        int i1 = 0;
#pragma unroll
        for (int e = 1; e < NEXP; e++) if (p[e] > p[i1]) i1 = e;
        int i2 = (i1 == 0) ? 1 : 0;
#pragma unroll
        for (int e = 0; e < NEXP; e++) if (e != i1 && p[e] > p[i2]) i2 = e;
        float s2 = p[i1] + p[i2];
        g_tope[t * 2 + 0] = i1;  g_topp[t * 2 + 0] = p[i1] / s2;
        g_tope[t * 2 + 1] = i2;  g_topp[t * 2 + 1] = p[i2] / s2;
        atomicAdd(&g_fcount[i1], 1);
        atomicAdd(&g_scount[i1], 1);
        atomicAdd(&g_scount[i2], 1);
#pragma unroll
        for (int e = 0; e < NEXP; e++) warpP[warp][e] = p[e];
    }
    __syncthreads();
    if (tid < NEXP) {
        float s = 0.f;
#pragma unroll
        for (int w = 0; w < 8; w++) s += warpP[w][tid];
        g_blockP[blockIdx.x * NEXP + tid] = s;
    }
}

// ---------------- offsets ----------------
__global__ void offsets_kernel() {
    if (threadIdx.x == 0) {
        int o = 0;
        for (int e = 0; e < NEXP; e++) {
            g_off[e] = o;
            g_cursor[e] = o;
            o += ((g_scount[e] + TM - 1) / TM) * TM;
        }
        g_off[NEXP] = o;
    }
}

// ---------------- scatter ----------------
__global__ void scatter_kernel() {
    int t = blockIdx.x * blockDim.x + threadIdx.x;
    if (t >= NTOK) return;
#pragma unroll
    for (int k = 0; k < 2; k++) {
        int e = g_tope[t * 2 + k];
        int pos = atomicAdd(&g_cursor[e], 1);
        g_perm_tok[pos] = t;
        g_pos[t * 2 + k] = pos;
    }
}

// ---------------- FFMA2 helper ----------------
__device__ __forceinline__ void ffma2(unsigned long long& c, unsigned long long a,
                                      unsigned long long b) {
    asm("fma.rn.f32x2 %0, %1, %2, %0;" : "+l"(c) : "l"(a), "l"(b));
}

// ---------------- GEMM1: hidden = relu(gather(x) @ w1[e]) ----------------
__global__ void __launch_bounds__(256, 2) gemm1_kernel(const float* __restrict__ x,
                                                       const float* __restrict__ w1) {
    __shared__ float As[2][TKK][2 * TM];   // 32 KB: duplicated pairs for f32x2
    __shared__ float Bs[2][TKK][TN];       // 16 KB

    int row0 = blockIdx.y * TM;
    if (row0 >= g_off[NEXP]) return;
    int e = 0;
#pragma unroll
    for (int q = 1; q < NEXP; q++) if (row0 >= g_off[q]) e = q;
    const float* B = w1 + (size_t)e * DMODEL * HID;
    int bn0 = blockIdx.x * TN;
    int tid = threadIdx.x;

    int ar = tid >> 1, ak = (tid & 1) * 8;          // A: row ar, k-offset ak (0/8)
    int bk = tid >> 4, btx = tid & 15;              // B: k-row bk, chunk pair btx / btx+16
    int tx = tid & 15, ty = tid >> 4;
    int tokA = g_perm_tok[row0 + ar];
    const float* Arow = (tokA >= 0) ? (x + (size_t)tokA * DMODEL + ak) : x;
    const float* Brow = B + (size_t)bk * HID + bn0 + 4 * btx;   // chunks at +0 and +64

    unsigned long long acc[8][4];
#pragma unroll
    for (int i = 0; i < 8; i++)
#pragma unroll
        for (int j = 0; j < 4; j++) acc[i][j] = 0ull;

    // prologue: tile 0
    {
        float4 a0 = make_float4(0.f, 0.f, 0.f, 0.f), a1 = a0;
        if (tokA >= 0) { a0 = *(const float4*)(Arow); a1 = *(const float4*)(Arow + 4); }
#pragma unroll
        for (int j = 0; j < 4; j++) {
            float v0 = (&a0.x)[j], v1 = (&a1.x)[j];
            *(float2*)&As[0][ak + j][2 * ar] = make_float2(v0, v0);
            *(float2*)&As[0][ak + 4 + j][2 * ar] = make_float2(v1, v1);
        }
        *(float4*)&Bs[0][bk][4 * btx] = *(const float4*)Brow;
        *(float4*)&Bs[0][bk][64 + 4 * btx] = *(const float4*)(Brow + 64);
    }
    __syncthreads();

    const int nk = DMODEL / TKK;   // 64
    for (int kt = 0; kt < nk; kt++) {
        int buf = kt & 1;
        float4 a0n, a1n, b0n, b1n;
        bool more = (kt + 1 < nk);
        if (more) {
            a0n = make_float4(0.f, 0.f, 0.f, 0.f); a1n = a0n;
            if (tokA >= 0) {
                a0n = *(const float4*)(Arow + (kt + 1) * TKK);
                a1n = *(const float4*)(Arow + (kt + 1) * TKK + 4);
            }
            const float* bp = Brow + (size_t)(kt + 1) * TKK * HID;
            b0n = *(const float4*)bp;
            b1n = *(const float4*)(bp + 64);
        }
#pragma unroll
        for (int kk = 0; kk < TKK; kk++) {
            unsigned long long a8[8], b4[4];
#pragma unroll
            for (int i = 0; i < 4; i++) {
                ulonglong2 t = *(const ulonglong2*)&As[buf][kk][2 * (ty * 8 + 2 * i)];
                a8[2 * i] = t.x;  a8[2 * i + 1] = t.y;
            }
            {
                ulonglong2 t0 = *(const ulonglong2*)&Bs[buf][kk][4 * tx];
                ulonglong2 t1 = *(const ulonglong2*)&Bs[buf][kk][64 + 4 * tx];
                b4[0] = t0.x;  b4[1] = t0.y;  b4[2] = t1.x;  b4[3] = t1.y;
            }
#pragma unroll
            for (int i = 0; i < 8; i++)
#pragma unroll
                for (int j = 0; j < 4; j++) ffma2(acc[i][j], a8[i], b4[j]);
        }
        if (more) {
            int nb = buf ^ 1;
#pragma unroll
            for (int j = 0; j < 4; j++) {
                float v0 = (&a0n.x)[j], v1 = (&a1n.x)[j];
                *(float2*)&As[nb][ak + j][2 * ar] = make_float2(v0, v0);
                *(float2*)&As[nb][ak + 4 + j][2 * ar] = make_float2(v1, v1);
            }
            *(float4*)&Bs[nb][bk][4 * btx] = b0n;
            *(float4*)&Bs[nb][bk][64 + 4 * btx] = b1n;
            __syncthreads();
        }
    }

    // epilogue: relu + store (cols 4tx..4tx+3 and 64+4tx..+3)
#pragma unroll
    for (int i = 0; i < 8; i++) {
        int row = row0 + ty * 8 + i;
        float* dst = g_hidden + (size_t)row * HID + bn0;
        float2 p0 = *(float2*)&acc[i][0];
        float2 p1 = *(float2*)&acc[i][1];
        float2 p2 = *(float2*)&acc[i][2];
        float2 p3 = *(float2*)&acc[i][3];
        float4 v0 = make_float4(fmaxf(p0.x, 0.f), fmaxf(p0.y, 0.f),
                                fmaxf(p1.x, 0.f), fmaxf(p1.y, 0.f));
        float4 v1 = make_float4(fmaxf(p2.x, 0.f), fmaxf(p2.y, 0.f),
                                fmaxf(p3.x, 0.f), fmaxf(p3.y, 0.f));
        *(float4*)(dst + 4 * tx) = v0;
        *(float4*)(dst + 64 + 4 * tx) = v1;
    }
}

// ---------------- GEMM2: expout = hidden @ w2[e] ----------------
__global__ void __launch_bounds__(256, 2) gemm2_kernel(const float* __restrict__ w2) {
    __shared__ float As[2][TKK][2 * TM];
    __shared__ float Bs[2][TKK][TN];

    int row0 = blockIdx.y * TM;
    if (row0 >= g_off[NEXP]) return;
    int e = 0;
#pragma unroll
    for (int q = 1; q < NEXP; q++) if (row0 >= g_off[q]) e = q;
    const float* B = w2 + (size_t)e * HID * DMODEL;
    int bn0 = blockIdx.x * TN;
    int tid = threadIdx.x;

    int ar = tid >> 1, ak = (tid & 1) * 8;
    int bk = tid >> 4, btx = tid & 15;
    int tx = tid & 15, ty = tid >> 4;
    const float* Arow = g_hidden + (size_t)(row0 + ar) * HID + ak;
    const float* Brow = B + (size_t)bk * DMODEL + bn0 + 4 * btx;

    unsigned long long acc[8][4];
#pragma unroll
    for (int i = 0; i < 8; i++)
#pragma unroll
        for (int j = 0; j < 4; j++) acc[i][j] = 0ull;

    {
        float4 a0 = *(const float4*)(Arow);
        float4 a1 = *(const float4*)(Arow + 4);
#pragma unroll
        for (int j = 0; j < 4; j++) {
            float v0 = (&a0.x)[j], v1 = (&a1.x)[j];
            *(float2*)&As[0][ak + j][2 * ar] = make_float2(v0, v0);
            *(float2*)&As[0][ak + 4 + j][2 * ar] = make_float2(v1, v1);
        }
        *(float4*)&Bs[0][bk][4 * btx] = *(const float4*)Brow;
        *(float4*)&Bs[0][bk][64 + 4 * btx] = *(const float4*)(Brow + 64);
    }
    __syncthreads();

    const int nk = HID / TKK;   // 128
    for (int kt = 0; kt < nk; kt++) {
        int buf = kt & 1;
        float4 a0n, a1n, b0n, b1n;
        bool more = (kt + 1 < nk);
        if (more) {
            a0n = *(const float4*)(Arow + (kt + 1) * TKK);
            a1n = *(const float4*)(Arow + (kt + 1) * TKK + 4);
            const float* bp = Brow + (size_t)(kt + 1) * TKK * DMODEL;
            b0n = *(const float4*)bp;
            b1n = *(const float4*)(bp + 64);
        }
#pragma unroll
        for (int kk = 0; kk < TKK; kk++) {
            unsigned long long a8[8], b4[4];
#pragma unroll
            for (int i = 0; i < 4; i++) {
                ulonglong2 t = *(const ulonglong2*)&As[buf][kk][2 * (ty * 8 + 2 * i)];
                a8[2 * i] = t.x;  a8[2 * i + 1] = t.y;
            }
            {
                ulonglong2 t0 = *(const ulonglong2*)&Bs[buf][kk][4 * tx];
                ulonglong2 t1 = *(const ulonglong2*)&Bs[buf][kk][64 + 4 * tx];
                b4[0] = t0.x;  b4[1] = t0.y;  b4[2] = t1.x;  b4[3] = t1.y;
            }
#pragma unroll
            for (int i = 0; i < 8; i++)
#pragma unroll
                for (int j = 0; j < 4; j++) ffma2(acc[i][j], a8[i], b4[j]);
        }
        if (more) {
            int nb = buf ^ 1;
#pragma unroll
            for (int j = 0; j < 4; j++) {
                float v0 = (&a0n.x)[j], v1 = (&a1n.x)[j];
                *(float2*)&As[nb][ak + j][2 * ar] = make_float2(v0, v0);
                *(float2*)&As[nb][ak + 4 + j][2 * ar] = make_float2(v1, v1);
            }
            *(float4*)&Bs[nb][bk][4 * btx] = b0n;
            *(float4*)&Bs[nb][bk][64 + 4 * btx] = b1n;
            __syncthreads();
        }
    }

#pragma unroll
    for (int i = 0; i < 8; i++) {
        int row = row0 + ty * 8 + i;
        float* dst = g_expout + (size_t)row * DMODEL + bn0;
        float2 p0 = *(float2*)&acc[i][0];
        float2 p1 = *(float2*)&acc[i][1];
        float2 p2 = *(float2*)&acc[i][2];
        float2 p3 = *(float2*)&acc[i][3];
        *(float4*)(dst + 4 * tx) = make_float4(p0.x, p0.y, p1.x, p1.y);
        *(float4*)(dst + 64 + 4 * tx) = make_float4(p2.x, p2.y, p3.x, p3.y);
    }
}

// ---------------- combine ----------------
__global__ void combine_kernel(float* __restrict__ out) {
    int idx = blockIdx.x * blockDim.x + threadIdx.x;
    if (idx >= NTOK * (DMODEL / 4)) return;
    int t = idx >> 8;
    int c = idx & 255;
    float p0 = g_topp[t * 2 + 0], p1 = g_topp[t * 2 + 1];
    size_t r0 = (size_t)g_pos[t * 2 + 0] * (DMODEL / 4);
    size_t r1 = (size_t)g_pos[t * 2 + 1] * (DMODEL / 4);
    const float4* buf = (const float4*)g_expout;
    float4 a = buf[r0 + c];
    float4 b = buf[r1 + c];
    float4 o;
    o.x = p0 * a.x + p1 * b.x;
    o.y = p0 * a.y + p1 * b.y;
    o.z = p0 * a.z + p1 * b.z;
    o.w = p0 * a.w + p1 * b.w;
    ((float4*)out)[idx] = o;
}

// ---------------- aux loss ----------------
__global__ void aux_kernel(float* __restrict__ out, int out_size) {
    __shared__ float P[NEXP];
    int e = threadIdx.x;
    if (e < NEXP) {
        float s = 0.f;
        for (int b = 0; b < NTOK / 8; b++) s += g_blockP[b * NEXP + e];
        P[e] = s * (1.0f / NTOK);
    }
    __syncthreads();
    if (threadIdx.x == 0 && out_size > OUT_ELEMS) {
        float aux = 0.f;
        for (int q = 0; q < NEXP; q++)
            aux += ((float)g_fcount[q] * (1.0f / NTOK)) * P[q];
        aux *= 0.01f * NEXP;
        out[OUT_ELEMS] = aux;
    }
}

// ---------------- launch ----------------
extern "C" void kernel_launch(void* const* d_in, const int* in_sizes, int n_in,
                              void* d_out, int out_size) {
    const float* x      = (const float*)d_in[0];
    const float* gate_w = (const float*)d_in[1];
    const float* w1     = (const float*)d_in[2];
    const float* w2     = (const float*)d_in[3];
    float* out = (float*)d_out;

    init_kernel<<<(MAXR + 255) / 256, 256>>>();
    router_kernel<<<NTOK / 8, 256>>>(x, gate_w);
    offsets_kernel<<<1, 32>>>();
    scatter_kernel<<<(NTOK + 255) / 256, 256>>>();

    dim3 g1(HID / TN, MAXR / TM);      // (16, 136)
    gemm1_kernel<<<g1, 256>>>(x, w1);
    dim3 g2(DMODEL / TN, MAXR / TM);   // (8, 136)
    gemm2_kernel<<<g2, 256>>>(w2);

    combine_kernel<<<(NTOK * (DMODEL / 4) + 255) / 256, 256>>>(out);
    aux_kernel<<<1, 32>>>(out, out_size);
}

// round 10
// speedup vs baseline: 1.3234x; 1.0025x over previous
#include <cuda_runtime.h>
#include <cstdint>

// Problem constants
#define NTOK   8192        // B*S = 4*2048
#define DMODEL 1024
#define NEXP   8
#define HID    2048
#define TOPK   2
#define TM     128
#define TN     128
#define TKK    16
#define MAXR   (NTOK*TOPK + NEXP*TM)   // 17408
#define NROWT  (MAXR/TM)               // 136 row tiles
#define T1_TILES ((HID/TN) * NROWT)    // 16*136 = 2176
#define T2_TILES ((DMODEL/TN) * NROWT) // 8*136  = 1088
#define OUT_ELEMS (NTOK*DMODEL)
#define PERSIST_CTAS 304               // 152 SM * 2

// ---------------- device scratch (no allocation allowed) ----------------
__device__ int   g_tope[NTOK*2];
__device__ float g_topp[NTOK*2];
__device__ int   g_pos[NTOK*2];
__device__ int   g_perm_tok[MAXR];
__device__ int   g_fcount[NEXP];
__device__ int   g_scount[NEXP];
__device__ int   g_off[NEXP+1];
__device__ int   g_cursor[NEXP];
__device__ float g_blockP[(NTOK/8)*NEXP];
__device__ int   g_tile_ctr;
__device__ int   g_ready[NROWT];
__device__ float g_hidden[(size_t)MAXR*HID];
__device__ float g_expout[(size_t)MAXR*DMODEL];

// ---------------- init ----------------
__global__ void init_kernel() {
    int i = blockIdx.x * blockDim.x + threadIdx.x;
    if (i < MAXR) g_perm_tok[i] = -1;
    if (i < NEXP) { g_fcount[i] = 0; g_scount[i] = 0; }
    if (i < NROWT) g_ready[i] = 0;
    if (i == 0) g_tile_ctr = 0;
}

// ---------------- router ----------------
__global__ void __launch_bounds__(256) router_kernel(const float* __restrict__ x,
                                                     const float* __restrict__ gate_w) {
    __shared__ float sg[NEXP * DMODEL];
    __shared__ float warpP[8][NEXP];
    int tid = threadIdx.x;
    for (int i = tid; i < NEXP * DMODEL; i += 256) sg[i] = gate_w[i];
    __syncthreads();

    int warp = tid >> 5, lane = tid & 31;
    int t = blockIdx.x * 8 + warp;
    const float* xr = x + (size_t)t * DMODEL;

    float acc[NEXP];
#pragma unroll
    for (int e = 0; e < NEXP; e++) acc[e] = 0.f;
    for (int j = 0; j < DMODEL / 32; j++) {
        float v = xr[j * 32 + lane];
#pragma unroll
        for (int e = 0; e < NEXP; e++) acc[e] += v * sg[e * DMODEL + j * 32 + lane];
    }
#pragma unroll
    for (int e = 0; e < NEXP; e++)
#pragma unroll
        for (int o = 16; o > 0; o >>= 1) acc[e] += __shfl_xor_sync(0xffffffffu, acc[e], o);

    if (lane == 0) {
        float m = acc[0];
#pragma unroll
        for (int e = 1; e < NEXP; e++) m = fmaxf(m, acc[e]);
        float p[NEXP], s = 0.f;
#pragma unroll
        for (int e = 0; e < NEXP; e++) { p[e] = __expf(acc[e] - m); s += p[e]; }
        float inv = 1.f / s;
#pragma unroll
        for (int e = 0; e < NEXP; e++) p[e] *= inv;
        int i1 = 0;
#pragma unroll
        for (int e = 1; e < NEXP; e++) if (p[e] > p[i1]) i1 = e;
        int i2 = (i1 == 0) ? 1 : 0;
#pragma unroll
        for (int e = 0; e < NEXP; e++) if (e != i1 && p[e] > p[i2]) i2 = e;
        float s2 = p[i1] + p[i2];
        g_tope[t * 2 + 0] = i1;  g_topp[t * 2 + 0] = p[i1] / s2;
        g_tope[t * 2 + 1] = i2;  g_topp[t * 2 + 1] = p[i2] / s2;
        atomicAdd(&g_fcount[i1], 1);
        atomicAdd(&g_scount[i1], 1);
        atomicAdd(&g_scount[i2], 1);
#pragma unroll
        for (int e = 0; e < NEXP; e++) warpP[warp][e] = p[e];
    }
    __syncthreads();
    if (tid < NEXP) {
        float s = 0.f;
#pragma unroll
        for (int w = 0; w < 8; w++) s += warpP[w][tid];
        g_blockP[blockIdx.x * NEXP + tid] = s;
    }
}

// ---------------- offsets ----------------
__global__ void offsets_kernel() {
    if (threadIdx.x == 0) {
        int o = 0;
        for (int e = 0; e < NEXP; e++) {
            g_off[e] = o;
            g_cursor[e] = o;
            o += ((g_scount[e] + TM - 1) / TM) * TM;
        }
        g_off[NEXP] = o;
    }
}

// ---------------- scatter ----------------
__global__ void scatter_kernel() {
    int t = blockIdx.x * blockDim.x + threadIdx.x;
    if (t >= NTOK) return;
#pragma unroll
    for (int k = 0; k < 2; k++) {
        int e = g_tope[t * 2 + k];
        int pos = atomicAdd(&g_cursor[e], 1);
        g_perm_tok[pos] = t;
        g_pos[t * 2 + k] = pos;
    }
}

// ---------------- helpers ----------------
__device__ __forceinline__ void ffma2(unsigned long long& c, unsigned long long a,
                                      unsigned long long b) {
    asm("fma.rn.f32x2 %0, %1, %2, %0;" : "+l"(c) : "l"(a), "l"(b));
}
__device__ __forceinline__ int ld_acquire(const int* p) {
    int v;
    asm volatile("ld.acquire.gpu.s32 %0, [%1];" : "=r"(v) : "l"(p) : "memory");
    return v;
}

// ---------------- one 128x128 GEMM tile (R9 mapping, bank-conflict-free) ----------------
template<bool GATHER, bool RELU, int KD, int NO>
__device__ __forceinline__ void gemm_tile(
    const float* __restrict__ Asrc, const float* __restrict__ W,
    float* __restrict__ Out, int row0, int bn0,
    float (*As)[TKK][2 * TM], float (*Bs)[TKK][TN])
{
    int e = 0;
#pragma unroll
    for (int q = 1; q < NEXP; q++) if (row0 >= g_off[q]) e = q;
    const float* B = W + (size_t)e * KD * NO;
    int tid = threadIdx.x;

    int ar = tid >> 1, ak = (tid & 1) * 8;
    int bk = tid >> 4, btx = tid & 15;
    int tx = tid & 15, ty = tid >> 4;
    int tokA = 0;
    const float* Arow;
    if (GATHER) {
        tokA = g_perm_tok[row0 + ar];
        Arow = (tokA >= 0) ? (Asrc + (size_t)tokA * KD + ak) : Asrc;
    } else {
        Arow = Asrc + (size_t)(row0 + ar) * KD + ak;
    }
    const float* Brow = B + (size_t)bk * NO + bn0 + 4 * btx;

    unsigned long long acc[8][4];
#pragma unroll
    for (int i = 0; i < 8; i++)
#pragma unroll
        for (int j = 0; j < 4; j++) acc[i][j] = 0ull;

    // prologue: tile 0
    {
        float4 a0 = make_float4(0.f, 0.f, 0.f, 0.f), a1 = a0;
        if (!GATHER || tokA >= 0) { a0 = *(const float4*)(Arow); a1 = *(const float4*)(Arow + 4); }
#pragma unroll
        for (int j = 0; j < 4; j++) {
            float v0 = (&a0.x)[j], v1 = (&a1.x)[j];
            *(float2*)&As[0][ak + j][2 * ar] = make_float2(v0, v0);
            *(float2*)&As[0][ak + 4 + j][2 * ar] = make_float2(v1, v1);
        }
        *(float4*)&Bs[0][bk][4 * btx] = *(const float4*)Brow;
        *(float4*)&Bs[0][bk][64 + 4 * btx] = *(const float4*)(Brow + 64);
    }
    __syncthreads();

    const int nk = KD / TKK;
    for (int kt = 0; kt < nk; kt++) {
        int buf = kt & 1;
        float4 a0n, a1n, b0n, b1n;
        bool more = (kt + 1 < nk);
        if (more) {
            a0n = make_float4(0.f, 0.f, 0.f, 0.f); a1n = a0n;
            if (!GATHER || tokA >= 0) {
                a0n = *(const float4*)(Arow + (kt + 1) * TKK);
                a1n = *(const float4*)(Arow + (kt + 1) * TKK + 4);
            }
            const float* bp = Brow + (size_t)(kt + 1) * TKK * NO;
            b0n = *(const float4*)bp;
            b1n = *(const float4*)(bp + 64);
        }
#pragma unroll
        for (int kk = 0; kk < TKK; kk++) {
            unsigned long long a8[8], b4[4];
#pragma unroll
            for (int i = 0; i < 4; i++) {
                ulonglong2 t2 = *(const ulonglong2*)&As[buf][kk][2 * (ty * 8 + 2 * i)];
                a8[2 * i] = t2.x;  a8[2 * i + 1] = t2.y;
            }
            {
                ulonglong2 t0 = *(const ulonglong2*)&Bs[buf][kk][4 * tx];
                ulonglong2 t1 = *(const ulonglong2*)&Bs[buf][kk][64 + 4 * tx];
                b4[0] = t0.x;  b4[1] = t0.y;  b4[2] = t1.x;  b4[3] = t1.y;
            }
#pragma unroll
            for (int i = 0; i < 8; i++)
#pragma unroll
                for (int j = 0; j < 4; j++) ffma2(acc[i][j], a8[i], b4[j]);
        }
        if (more) {
            int nb = buf ^ 1;
#pragma unroll
            for (int j = 0; j < 4; j++) {
                float v0 = (&a0n.x)[j], v1 = (&a1n.x)[j];
                *(float2*)&As[nb][ak + j][2 * ar] = make_float2(v0, v0);
                *(float2*)&As[nb][ak + 4 + j][2 * ar] = make_float2(v1, v1);
            }
            *(float4*)&Bs[nb][bk][4 * btx] = b0n;
            *(float4*)&Bs[nb][bk][64 + 4 * btx] = b1n;
            __syncthreads();
        }
    }

    // epilogue
#pragma unroll
    for (int i = 0; i < 8; i++) {
        int row = row0 + ty * 8 + i;
        float* dst = Out + (size_t)row * NO + bn0;
        float2 p0 = *(float2*)&acc[i][0];
        float2 p1 = *(float2*)&acc[i][1];
        float2 p2 = *(float2*)&acc[i][2];
        float2 p3 = *(float2*)&acc[i][3];
        float4 v0, v1;
        if (RELU) {
            v0 = make_float4(fmaxf(p0.x, 0.f), fmaxf(p0.y, 0.f),
                             fmaxf(p1.x, 0.f), fmaxf(p1.y, 0.f));
            v1 = make_float4(fmaxf(p2.x, 0.f), fmaxf(p2.y, 0.f),
                             fmaxf(p3.x, 0.f), fmaxf(p3.y, 0.f));
        } else {
            v0 = make_float4(p0.x, p0.y, p1.x, p1.y);
            v1 = make_float4(p2.x, p2.y, p3.x, p3.y);
        }
        *(float4*)(dst + 4 * tx) = v0;
        *(float4*)(dst + 64 + 4 * tx) = v1;
    }
}

// ---------------- fused persistent GEMM1+GEMM2 with tile queue ----------------
__global__ void __launch_bounds__(256, 2) moe_fused_gemm(
    const float* __restrict__ x, const float* __restrict__ w1,
    const float* __restrict__ w2)
{
    __shared__ float As[2][TKK][2 * TM];   // 32 KB
    __shared__ float Bs[2][TKK][TN];       // 16 KB
    __shared__ int s_t;
    int tid = threadIdx.x;
    int rows_used = g_off[NEXP];

    while (true) {
        __syncthreads();                       // smem reuse + s_t protection
        if (tid == 0) s_t = atomicAdd(&g_tile_ctr, 1);
        __syncthreads();
        int t = s_t;
        if (t >= T1_TILES + T2_TILES) return;

        if (t < T1_TILES) {
            // GEMM1 tile: hidden = relu(gather(x) @ w1[e])
            int y = t >> 4, xblk = t & 15;     // 16 N-tiles
            int row0 = y * TM;
            if (row0 < rows_used) {
                gemm_tile<true, true, DMODEL, HID>(x, w1, g_hidden, row0, xblk * TN, As, Bs);
            }
            // producer release: all threads' stores, then counter bump
            __threadfence();
            __syncthreads();
            if (tid == 0) atomicAdd(&g_ready[y], 1);
        } else {
            // GEMM2 tile: expout = hidden @ w2[e]
            int idx = t - T1_TILES;
            int y = idx >> 3, xblk = idx & 7;  // 8 N-tiles
            int row0 = y * TM;
            if (row0 >= rows_used) continue;
            if (tid == 0) {
                while (ld_acquire(&g_ready[y]) < 16) __nanosleep(64);
            }
            __syncthreads();                   // broadcast readiness
            gemm_tile<false, false, HID, DMODEL>(g_hidden, w2, g_expout, row0, xblk * TN, As, Bs);
        }
    }
}

// ---------------- combine ----------------
__global__ void combine_kernel(float* __restrict__ out) {
    int idx = blockIdx.x * blockDim.x + threadIdx.x;
    if (idx >= NTOK * (DMODEL / 4)) return;
    int t = idx >> 8;
    int c = idx & 255;
    float p0 = g_topp[t * 2 + 0], p1 = g_topp[t * 2 + 1];
    size_t r0 = (size_t)g_pos[t * 2 + 0] * (DMODEL / 4);
    size_t r1 = (size_t)g_pos[t * 2 + 1] * (DMODEL / 4);
    const float4* buf = (const float4*)g_expout;
    float4 a = buf[r0 + c];
    float4 b = buf[r1 + c];
    float4 o;
    o.x = p0 * a.x + p1 * b.x;
    o.y = p0 * a.y + p1 * b.y;
    o.z = p0 * a.z + p1 * b.z;
    o.w = p0 * a.w + p1 * b.w;
    ((float4*)out)[idx] = o;
}

// ---------------- aux loss ----------------
__global__ void aux_kernel(float* __restrict__ out, int out_size) {
    __shared__ float P[NEXP];
    int e = threadIdx.x;
    if (e < NEXP) {
        float s = 0.f;
        for (int b = 0; b < NTOK / 8; b++) s += g_blockP[b * NEXP + e];
        P[e] = s * (1.0f / NTOK);
    }
    __syncthreads();
    if (threadIdx.x == 0 && out_size > OUT_ELEMS) {
        float aux = 0.f;
        for (int q = 0; q < NEXP; q++)
            aux += ((float)g_fcount[q] * (1.0f / NTOK)) * P[q];
        aux *= 0.01f * NEXP;
        out[OUT_ELEMS] = aux;
    }
}

// ---------------- launch ----------------
extern "C" void kernel_launch(void* const* d_in, const int* in_sizes, int n_in,
                              void* d_out, int out_size) {
    const float* x      = (const float*)d_in[0];
    const float* gate_w = (const float*)d_in[1];
    const float* w1     = (const float*)d_in[2];
    const float* w2     = (const float*)d_in[3];
    float* out = (float*)d_out;

    init_kernel<<<(MAXR + 255) / 256, 256>>>();
    router_kernel<<<NTOK / 8, 256>>>(x, gate_w);
    offsets_kernel<<<1, 32>>>();
    scatter_kernel<<<(NTOK + 255) / 256, 256>>>();

    moe_fused_gemm<<<PERSIST_CTAS, 256>>>(x, w1, w2);

    combine_kernel<<<(NTOK * (DMODEL / 4) + 255) / 256, 256>>>(out);
    aux_kernel<<<1, 32>>>(out, out_size);
}